// round 3
// baseline (speedup 1.0000x reference)
#include <cuda_runtime.h>
#include <cuda_bf16.h>
#include <math.h>

#define NN 100000
#define NF 64
#define NC 40
#define NE 1600000

// scratch (allocation-free rule: device globals)
__device__ float g_y[NN * NC];     // x @ lin_l_w
__device__ float g_z[NN * NC];     // x @ lin_r_w + b
__device__ float g_agg[NN * NC];   // segment sum of g_y rows
__device__ float g_deg[NN];        // in-degree
__device__ int   g_is64;           // 1 if index buffer is int64, 0 if int32

// ---------------------------------------------------------------------------
// K0: detect index dtype. If int64 (values < 2^31), every odd 32-bit word of
// the first 128 words is zero. Random int32 indices in [0,100000) make that
// astronomically unlikely.
// ---------------------------------------------------------------------------
__global__ void k_detect(const int* __restrict__ idx32) {
    if (threadIdx.x == 0) {
        int odd_nonzero = 0;
        for (int i = 1; i < 128; i += 2)
            if (idx32[i] != 0) odd_nonzero++;
        g_is64 = (odd_nonzero == 0) ? 1 : 0;
    }
}

// ---------------------------------------------------------------------------
// K1: y = x@Wl, z = x@Wr + b; also zero agg/deg for this node range.
// ---------------------------------------------------------------------------
__global__ void __launch_bounds__(256) k_gemm(const float* __restrict__ x,
                                              const float* __restrict__ wl,
                                              const float* __restrict__ bl,
                                              const float* __restrict__ wr) {
    __shared__ float s_wl[NF * NC];
    __shared__ float s_wr[NF * NC];
    __shared__ float s_b[NC];
    __shared__ float s_x[64][NF + 1];   // +1 pad: avoid bank conflicts

    const int tid = threadIdx.x;
    for (int i = tid; i < NF * NC; i += 256) {
        s_wl[i] = wl[i];
        s_wr[i] = wr[i];
    }
    if (tid < NC) s_b[tid] = bl[tid];

    const int n0 = blockIdx.x * 64;
    for (int i = tid; i < 64 * NF; i += 256) {
        int r = i >> 6, k = i & 63;
        int n = n0 + r;
        s_x[r][k] = (n < NN) ? x[(size_t)n * NF + k] : 0.0f;
    }
    __syncthreads();

    for (int p = tid; p < 64 * NC; p += 256) {
        int r = p / NC, c = p % NC;
        int n = n0 + r;
        if (n >= NN) continue;
        float ya = 0.0f, za = 0.0f;
#pragma unroll
        for (int k = 0; k < NF; k++) {
            float xv = s_x[r][k];
            ya = fmaf(xv, s_wl[k * NC + c], ya);
            za = fmaf(xv, s_wr[k * NC + c], za);
        }
        g_y[n * NC + c] = ya;
        g_z[n * NC + c] = za + s_b[c];
        g_agg[n * NC + c] = 0.0f;
        if (c == 0) g_deg[n] = 0.0f;
    }
}

// ---------------------------------------------------------------------------
// K2: scatter. One thread per (edge, 4-col chunk): float4 gather from
// g_y[src] (16 MB, L2-resident) + 4 RED.ADDs into g_agg[dst].
// Handles both int32 and int64 index layouts via g_is64 (uniform branch).
// ---------------------------------------------------------------------------
__global__ void __launch_bounds__(256) k_scatter(const void* __restrict__ idx_raw) {
    long long t = (long long)blockIdx.x * 256 + threadIdx.x;
    if (t >= (long long)NE * 10) return;
    int e = (int)(t / 10);
    int chunk = (int)(t % 10);

    int src, dst;
    if (g_is64) {
        const long long* idx = (const long long*)idx_raw;
        src = (int)idx[e];
        dst = (int)idx[NE + e];
    } else {
        const int* idx = (const int*)idx_raw;
        src = idx[e];
        dst = idx[NE + e];
    }
    // defensive clamp: bad layout -> wrong answer (rel_err signal), not a crash
    src = min(max(src, 0), NN - 1);
    dst = min(max(dst, 0), NN - 1);

    const float4 v = *reinterpret_cast<const float4*>(&g_y[src * NC + chunk * 4]);
    float* o = &g_agg[dst * NC + chunk * 4];
    atomicAdd(o + 0, v.x);
    atomicAdd(o + 1, v.y);
    atomicAdd(o + 2, v.z);
    atomicAdd(o + 3, v.w);
    if (chunk == 0) atomicAdd(&g_deg[dst], 1.0f);
}

// ---------------------------------------------------------------------------
// K3: out = log_softmax(agg/max(deg,1) + z). Warp per node.
// ---------------------------------------------------------------------------
__global__ void __launch_bounds__(256) k_final(float* __restrict__ out) {
    int gtid = blockIdx.x * 256 + threadIdx.x;
    int node = gtid >> 5;
    int lane = threadIdx.x & 31;
    if (node >= NN) return;

    float inv = 1.0f / fmaxf(g_deg[node], 1.0f);
    const float NEG = -3.0e38f;

    int c0 = lane;
    int c1 = lane + 32;
    float va = (c0 < NC) ? fmaf(g_agg[node * NC + c0], inv, g_z[node * NC + c0]) : NEG;
    float vb = (c1 < NC) ? fmaf(g_agg[node * NC + c1], inv, g_z[node * NC + c1]) : NEG;

    float m = fmaxf(va, vb);
#pragma unroll
    for (int off = 16; off > 0; off >>= 1)
        m = fmaxf(m, __shfl_xor_sync(0xFFFFFFFFu, m, off));

    float s = ((c0 < NC) ? __expf(va - m) : 0.0f) + ((c1 < NC) ? __expf(vb - m) : 0.0f);
#pragma unroll
    for (int off = 16; off > 0; off >>= 1)
        s += __shfl_xor_sync(0xFFFFFFFFu, s, off);

    float lse = m + logf(s);
    if (c0 < NC) out[node * NC + c0] = va - lse;
    if (c1 < NC) out[node * NC + c1] = vb - lse;
}

extern "C" void kernel_launch(void* const* d_in, const int* in_sizes, int n_in,
                              void* d_out, int out_size) {
    const float* x   = (const float*)d_in[0];
    const void*  idx = d_in[1];
    const float* wl  = (const float*)d_in[2];
    const float* bl  = (const float*)d_in[3];
    const float* wr  = (const float*)d_in[4];
    float* out = (float*)d_out;

    k_detect<<<1, 32>>>((const int*)idx);
    k_gemm<<<(NN + 63) / 64, 256>>>(x, wl, bl, wr);

    long long scatter_threads = (long long)NE * 10;
    int scatter_blocks = (int)((scatter_threads + 255) / 256);
    k_scatter<<<scatter_blocks, 256>>>(idx);

    int final_blocks = (NN * 32 + 255) / 256;
    k_final<<<final_blocks, 256>>>(out);
}

// round 4
// speedup vs baseline: 1.3191x; 1.3191x over previous
#include <cuda_runtime.h>
#include <cuda_bf16.h>
#include <math.h>

#define NN 100000
#define NF 64
#define NC 40
#define NE 1600000

// scratch (allocation-free rule: device globals). 16B alignment required for
// float4 loads and red.global.add.v4.f32.
__device__ __align__(16) float g_y[NN * NC];     // x @ lin_l_w
__device__ __align__(16) float g_z[NN * NC];     // x @ lin_r_w + b
__device__ __align__(16) float g_agg[NN * NC];   // segment sum of g_y rows
__device__ float g_deg[NN];                      // in-degree
__device__ int   g_is64;                         // 1 if index is int64, else int32

// ---------------------------------------------------------------------------
// K0: detect index dtype (int64 -> odd 32-bit words of small indices are 0).
// ---------------------------------------------------------------------------
__global__ void k_detect(const int* __restrict__ idx32) {
    if (threadIdx.x == 0) {
        int odd_nonzero = 0;
        for (int i = 1; i < 128; i += 2)
            if (idx32[i] != 0) odd_nonzero++;
        g_is64 = (odd_nonzero == 0) ? 1 : 0;
    }
}

// ---------------------------------------------------------------------------
// K1: y = x@Wl, z = x@Wr + b; zero agg/deg for this node range.
// ---------------------------------------------------------------------------
__global__ void __launch_bounds__(256) k_gemm(const float* __restrict__ x,
                                              const float* __restrict__ wl,
                                              const float* __restrict__ bl,
                                              const float* __restrict__ wr) {
    __shared__ float s_wl[NF * NC];
    __shared__ float s_wr[NF * NC];
    __shared__ float s_b[NC];
    __shared__ float s_x[64][NF + 1];

    const int tid = threadIdx.x;
    for (int i = tid; i < NF * NC; i += 256) {
        s_wl[i] = wl[i];
        s_wr[i] = wr[i];
    }
    if (tid < NC) s_b[tid] = bl[tid];

    const int n0 = blockIdx.x * 64;
    for (int i = tid; i < 64 * NF; i += 256) {
        int r = i >> 6, k = i & 63;
        int n = n0 + r;
        s_x[r][k] = (n < NN) ? x[(size_t)n * NF + k] : 0.0f;
    }
    __syncthreads();

    for (int p = tid; p < 64 * NC; p += 256) {
        int r = p / NC, c = p % NC;
        int n = n0 + r;
        if (n >= NN) continue;
        float ya = 0.0f, za = 0.0f;
#pragma unroll
        for (int k = 0; k < NF; k++) {
            float xv = s_x[r][k];
            ya = fmaf(xv, s_wl[k * NC + c], ya);
            za = fmaf(xv, s_wr[k * NC + c], za);
        }
        g_y[n * NC + c] = ya;
        g_z[n * NC + c] = za + s_b[c];
        g_agg[n * NC + c] = 0.0f;
        if (c == 0) g_deg[n] = 0.0f;
    }
}

// ---------------------------------------------------------------------------
// K2: scatter. One thread per (edge, 4-col chunk): float4 gather from
// g_y[src] (L2-resident) + ONE red.global.add.v4.f32 into g_agg[dst].
// ---------------------------------------------------------------------------
__global__ void __launch_bounds__(256) k_scatter(const void* __restrict__ idx_raw) {
    long long t = (long long)blockIdx.x * 256 + threadIdx.x;
    if (t >= (long long)NE * 10) return;
    int e = (int)(t / 10);
    int chunk = (int)(t % 10);

    int src, dst;
    if (g_is64) {
        const long long* idx = (const long long*)idx_raw;
        src = (int)idx[e];
        dst = (int)idx[NE + e];
    } else {
        const int* idx = (const int*)idx_raw;
        src = idx[e];
        dst = idx[NE + e];
    }
    src = min(max(src, 0), NN - 1);
    dst = min(max(dst, 0), NN - 1);

    const float4 v = *reinterpret_cast<const float4*>(&g_y[src * NC + chunk * 4]);
    float* o = &g_agg[dst * NC + chunk * 4];
    asm volatile("red.global.add.v4.f32 [%0], {%1, %2, %3, %4};"
                 :: "l"(o), "f"(v.x), "f"(v.y), "f"(v.z), "f"(v.w)
                 : "memory");
    if (chunk == 0) atomicAdd(&g_deg[dst], 1.0f);
}

// ---------------------------------------------------------------------------
// K3: out = log_softmax(agg/max(deg,1) + z). Warp per node.
// ---------------------------------------------------------------------------
__global__ void __launch_bounds__(256) k_final(float* __restrict__ out) {
    int gtid = blockIdx.x * 256 + threadIdx.x;
    int node = gtid >> 5;
    int lane = threadIdx.x & 31;
    if (node >= NN) return;

    float inv = 1.0f / fmaxf(g_deg[node], 1.0f);
    const float NEG = -3.0e38f;

    int c0 = lane;
    int c1 = lane + 32;
    float va = (c0 < NC) ? fmaf(g_agg[node * NC + c0], inv, g_z[node * NC + c0]) : NEG;
    float vb = (c1 < NC) ? fmaf(g_agg[node * NC + c1], inv, g_z[node * NC + c1]) : NEG;

    float m = fmaxf(va, vb);
#pragma unroll
    for (int off = 16; off > 0; off >>= 1)
        m = fmaxf(m, __shfl_xor_sync(0xFFFFFFFFu, m, off));

    float s = ((c0 < NC) ? __expf(va - m) : 0.0f) + ((c1 < NC) ? __expf(vb - m) : 0.0f);
#pragma unroll
    for (int off = 16; off > 0; off >>= 1)
        s += __shfl_xor_sync(0xFFFFFFFFu, s, off);

    float lse = m + logf(s);
    if (c0 < NC) out[node * NC + c0] = va - lse;
    if (c1 < NC) out[node * NC + c1] = vb - lse;
}

extern "C" void kernel_launch(void* const* d_in, const int* in_sizes, int n_in,
                              void* d_out, int out_size) {
    const float* x   = (const float*)d_in[0];
    const void*  idx = d_in[1];
    const float* wl  = (const float*)d_in[2];
    const float* bl  = (const float*)d_in[3];
    const float* wr  = (const float*)d_in[4];
    float* out = (float*)d_out;

    k_detect<<<1, 32>>>((const int*)idx);
    k_gemm<<<(NN + 63) / 64, 256>>>(x, wl, bl, wr);

    long long scatter_threads = (long long)NE * 10;
    int scatter_blocks = (int)((scatter_threads + 255) / 256);
    k_scatter<<<scatter_blocks, 256>>>(idx);

    int final_blocks = (NN * 32 + 255) / 256;
    k_final<<<final_blocks, 256>>>(out);
}